// round 1
// baseline (speedup 1.0000x reference)
#include <cuda_runtime.h>
#include <math.h>

#define BATCH  8
#define LSEQ   4096
#define HDIM   256
#define PDIM   256
#define MTOT   (BATCH*LSEQ)     /* 32768 */
#define CHUNK  64
#define NCHUNK (LSEQ/CHUNK)     /* 64 */

// ---------------- scratch (static device arrays: allocation-free) ----------
__device__ float g_h  [MTOT*HDIM];
__device__ float g_bur[MTOT*PDIM];
__device__ float g_bui[MTOT*PDIM];
__device__ float g_Wr [PDIM*HDIM];
__device__ float g_Wi [PDIM*HDIM];
__device__ float g_ar [PDIM];
__device__ float g_ai [PDIM];
__device__ float g_Er [BATCH*NCHUNK*PDIM];
__device__ float g_Ei [BATCH*NCHUNK*PDIM];

// ---------------- params: lambda_bar and B_bar (double precision) ----------
__global__ void k_params(const float* __restrict__ llr, const float* __restrict__ lim,
                         const float* __restrict__ Btr, const float* __restrict__ Bti,
                         const float* __restrict__ ld)
{
    int p = threadIdx.x;
    __shared__ float sgr[PDIM], sgi[PDIM];

    double lr = -exp((double)llr[p]);
    double li = (double)lim[p];
    double d  = exp((double)ld[p]);
    double er = exp(lr * d);
    double cz = cos(li * d), sz = sin(li * d);
    double ar = er * cz, ai = er * sz;
    g_ar[p] = (float)ar;
    g_ai[p] = (float)ai;
    double den = lr*lr + li*li;
    double gr = ((ar - 1.0)*lr + ai*li) / den;
    double gi = (ai*lr - (ar - 1.0)*li) / den;
    sgr[p] = (float)gr; sgi[p] = (float)gi;
    __syncthreads();

    for (int idx = p; idx < PDIM*HDIM; idx += 256) {
        int pp = idx >> 8;
        float br = Btr[idx], bi = Bti[idx];
        g_Wr[idx] = sgr[pp]*br - sgi[pp]*bi;
        g_Wi[idx] = sgr[pp]*bi + sgi[pp]*br;
    }
}

// ---------------- LayerNorm: one warp per row ------------------------------
__global__ void k_ln(const float* __restrict__ u, const float* __restrict__ gamma,
                     const float* __restrict__ beta)
{
    int warp = threadIdx.x >> 5, lane = threadIdx.x & 31;
    int row  = blockIdx.x * 8 + warp;
    const float* ur = u + (size_t)row * HDIM;

    float v[8]; float sum = 0.f;
#pragma unroll
    for (int j = 0; j < 8; j++) { v[j] = ur[lane + 32*j]; sum += v[j]; }
#pragma unroll
    for (int o = 16; o; o >>= 1) sum += __shfl_xor_sync(0xffffffffu, sum, o);
    float mu = sum * (1.f/HDIM);

    float ss = 0.f;
#pragma unroll
    for (int j = 0; j < 8; j++) { float dd = v[j]-mu; ss += dd*dd; }
#pragma unroll
    for (int o = 16; o; o >>= 1) ss += __shfl_xor_sync(0xffffffffu, ss, o);
    float inv = rsqrtf(ss * (1.f/HDIM) + 1e-5f);

    float* hr = g_h + (size_t)row * HDIM;
#pragma unroll
    for (int j = 0; j < 8; j++) {
        int c = lane + 32*j;
        hr[c] = (v[j]-mu) * inv * __ldg(&gamma[c]) + __ldg(&beta[c]);
    }
}

// ---------------- GEMM1: Bu_{r,i} = h @ W_{r,i}^T --------------------------
// BM=128, BN=64, BK=8, 256 threads, 8x4 microtile x 2 output matrices.
__global__ __launch_bounds__(256) void k_gemm_bu()
{
    __shared__ float As [8][128];
    __shared__ float Bsr[8][64];
    __shared__ float Bsi[8][64];

    int tid = threadIdx.x;
    int bm  = blockIdx.y * 128;
    int bn  = blockIdx.x * 64;
    int ty  = tid >> 4, tx = tid & 15;

    float accr[8][4], acci[8][4];
#pragma unroll
    for (int i = 0; i < 8; i++)
#pragma unroll
        for (int j = 0; j < 4; j++) { accr[i][j] = 0.f; acci[i][j] = 0.f; }

    int am   = tid >> 1;
    int ak   = (tid & 1) << 2;
    int bmat = tid >> 7;
    int bni  = (tid & 127) >> 1;
    int bk   = (tid & 1) << 2;
    const float* Wm  = bmat ? g_Wi : g_Wr;
    float* BsSel     = bmat ? &Bsi[0][0] : &Bsr[0][0];

    for (int k0 = 0; k0 < HDIM; k0 += 8) {
        float4 av = *(const float4*)&g_h[(size_t)(bm + am)*HDIM + k0 + ak];
        float4 bv = *(const float4*)&Wm[(size_t)(bn + bni)*HDIM + k0 + bk];
        __syncthreads();
        As[ak+0][am]=av.x; As[ak+1][am]=av.y; As[ak+2][am]=av.z; As[ak+3][am]=av.w;
        BsSel[(bk+0)*64+bni]=bv.x; BsSel[(bk+1)*64+bni]=bv.y;
        BsSel[(bk+2)*64+bni]=bv.z; BsSel[(bk+3)*64+bni]=bv.w;
        __syncthreads();
#pragma unroll
        for (int k = 0; k < 8; k++) {
            float a[8], br[4], bi[4];
            *(float4*)&a[0] = *(float4*)&As[k][ty*8];
            *(float4*)&a[4] = *(float4*)&As[k][ty*8+4];
            *(float4*)&br[0] = *(float4*)&Bsr[k][tx*4];
            *(float4*)&bi[0] = *(float4*)&Bsi[k][tx*4];
#pragma unroll
            for (int i = 0; i < 8; i++)
#pragma unroll
                for (int j = 0; j < 4; j++) {
                    accr[i][j] = fmaf(a[i], br[j], accr[i][j]);
                    acci[i][j] = fmaf(a[i], bi[j], acci[i][j]);
                }
        }
    }
#pragma unroll
    for (int i = 0; i < 8; i++) {
        size_t m = (size_t)(bm + ty*8 + i);
        float4 vr = make_float4(accr[i][0], accr[i][1], accr[i][2], accr[i][3]);
        float4 vi = make_float4(acci[i][0], acci[i][1], acci[i][2], acci[i][3]);
        *(float4*)&g_bur[m*PDIM + bn + tx*4] = vr;
        *(float4*)&g_bui[m*PDIM + bn + tx*4] = vi;
    }
}

// ---------------- scan phase 1: chunk-local end states ---------------------
__global__ void k_scan_ends()
{
    int p = threadIdx.x;
    int c = blockIdx.x, b = blockIdx.y;
    float ar = g_ar[p], ai = g_ai[p];
    size_t base = ((size_t)b * LSEQ + (size_t)c * CHUNK) * PDIM + p;
    float sr = 0.f, si = 0.f;
#pragma unroll 4
    for (int l = 0; l < CHUNK; l++) {
        float xr = g_bur[base + (size_t)l*PDIM];
        float xi = g_bui[base + (size_t)l*PDIM];
        float nr = fmaf(ar, sr, fmaf(-ai, si, xr));
        float ni = fmaf(ar, si, fmaf( ai, sr, xi));
        sr = nr; si = ni;
    }
    int idx = (b*NCHUNK + c)*PDIM + p;
    g_Er[idx] = sr; g_Ei[idx] = si;
}

// ---------------- scan phase 2: prefix across chunks -----------------------
__global__ void k_scan_chain()
{
    int p = threadIdx.x, b = blockIdx.x;
    float ar = g_ar[p], ai = g_ai[p];
    // a^CHUNK via 6 complex squarings (CHUNK = 64)
    float tr = ar, ti = ai;
#pragma unroll
    for (int i = 0; i < 6; i++) { float nr = tr*tr - ti*ti; ti = 2.f*tr*ti; tr = nr; }
    float sr = 0.f, si = 0.f;
#pragma unroll 8
    for (int c = 0; c < NCHUNK; c++) {
        int idx = (b*NCHUNK + c)*PDIM + p;
        float er = g_Er[idx], ei = g_Ei[idx];
        g_Er[idx] = sr; g_Ei[idx] = si;        // state ENTERING chunk c
        float nr = fmaf(tr, sr, fmaf(-ti, si, er));
        si = fmaf(tr, si, fmaf( ti, sr, ei));
        sr = nr;
    }
}

// ---------------- scan phase 3: rescan with carry, write xs in place -------
__global__ void k_scan_write()
{
    int p = threadIdx.x;
    int c = blockIdx.x, b = blockIdx.y;
    float ar = g_ar[p], ai = g_ai[p];
    int cidx = (b*NCHUNK + c)*PDIM + p;
    float sr = g_Er[cidx], si = g_Ei[cidx];
    size_t base = ((size_t)b * LSEQ + (size_t)c * CHUNK) * PDIM + p;
#pragma unroll 4
    for (int l = 0; l < CHUNK; l++) {
        float xr = g_bur[base + (size_t)l*PDIM];
        float xi = g_bui[base + (size_t)l*PDIM];
        float nr = fmaf(ar, sr, fmaf(-ai, si, xr));
        float ni = fmaf(ar, si, fmaf( ai, sr, xi));
        sr = nr; si = ni;
        g_bur[base + (size_t)l*PDIM] = sr;
        g_bui[base + (size_t)l*PDIM] = si;
    }
}

// ---------------- GEMM2: y = xs_r@Cr^T - xs_i@Ci^T; out = u + gelu(y) ------
__device__ __forceinline__ float gelu_tanh(float x)
{
    float x3 = x*x*x;
    float t = tanhf(0.7978845608028654f * fmaf(0.044715f, x3, x));
    return 0.5f * x * (1.f + t);
}

__global__ __launch_bounds__(256) void k_gemm_out(const float* __restrict__ Cr,
                                                  const float* __restrict__ Ci,
                                                  const float* __restrict__ U,
                                                  float* __restrict__ out)
{
    __shared__ float Asr[8][128];
    __shared__ float Asi[8][128];
    __shared__ float Bsr[8][64];
    __shared__ float Bsi[8][64];

    int tid = threadIdx.x;
    int bm  = blockIdx.y * 128;
    int bn  = blockIdx.x * 64;
    int ty  = tid >> 4, tx = tid & 15;

    float acc[8][4];
#pragma unroll
    for (int i = 0; i < 8; i++)
#pragma unroll
        for (int j = 0; j < 4; j++) acc[i][j] = 0.f;

    int am   = tid >> 1;
    int ak   = (tid & 1) << 2;
    int bmat = tid >> 7;
    int bni  = (tid & 127) >> 1;
    int bk   = (tid & 1) << 2;
    const float* Cm = bmat ? Ci : Cr;
    float* BsSel    = bmat ? &Bsi[0][0] : &Bsr[0][0];

    for (int k0 = 0; k0 < PDIM; k0 += 8) {
        float4 avr = *(const float4*)&g_bur[(size_t)(bm + am)*PDIM + k0 + ak];
        float4 avi = *(const float4*)&g_bui[(size_t)(bm + am)*PDIM + k0 + ak];
        float4 bv  = *(const float4*)&Cm[(size_t)(bn + bni)*PDIM + k0 + bk];
        __syncthreads();
        Asr[ak+0][am]=avr.x; Asr[ak+1][am]=avr.y; Asr[ak+2][am]=avr.z; Asr[ak+3][am]=avr.w;
        Asi[ak+0][am]=avi.x; Asi[ak+1][am]=avi.y; Asi[ak+2][am]=avi.z; Asi[ak+3][am]=avi.w;
        BsSel[(bk+0)*64+bni]=bv.x; BsSel[(bk+1)*64+bni]=bv.y;
        BsSel[(bk+2)*64+bni]=bv.z; BsSel[(bk+3)*64+bni]=bv.w;
        __syncthreads();
#pragma unroll
        for (int k = 0; k < 8; k++) {
            float xr[8], xi[8], cr[4], cim[4];
            *(float4*)&xr[0] = *(float4*)&Asr[k][ty*8];
            *(float4*)&xr[4] = *(float4*)&Asr[k][ty*8+4];
            *(float4*)&xi[0] = *(float4*)&Asi[k][ty*8];
            *(float4*)&xi[4] = *(float4*)&Asi[k][ty*8+4];
            *(float4*)&cr[0]  = *(float4*)&Bsr[k][tx*4];
            *(float4*)&cim[0] = *(float4*)&Bsi[k][tx*4];
#pragma unroll
            for (int i = 0; i < 8; i++)
#pragma unroll
                for (int j = 0; j < 4; j++) {
                    acc[i][j] = fmaf(xr[i],  cr[j],  acc[i][j]);
                    acc[i][j] = fmaf(-xi[i], cim[j], acc[i][j]);
                }
        }
    }
#pragma unroll
    for (int i = 0; i < 8; i++) {
        size_t m = (size_t)(bm + ty*8 + i);
        size_t o = m*HDIM + bn + tx*4;
        float4 uv = *(const float4*)&U[o];
        float4 r;
        r.x = uv.x + gelu_tanh(acc[i][0]);
        r.y = uv.y + gelu_tanh(acc[i][1]);
        r.z = uv.z + gelu_tanh(acc[i][2]);
        r.w = uv.w + gelu_tanh(acc[i][3]);
        *(float4*)&out[o] = r;
    }
}

// ---------------- launch ---------------------------------------------------
extern "C" void kernel_launch(void* const* d_in, const int* in_sizes, int n_in,
                              void* d_out, int out_size)
{
    const float* u    = (const float*)d_in[0];
    const float* llr  = (const float*)d_in[1];
    const float* lim  = (const float*)d_in[2];
    const float* Btr  = (const float*)d_in[3];
    const float* Bti  = (const float*)d_in[4];
    const float* Ctr  = (const float*)d_in[5];
    const float* Cti  = (const float*)d_in[6];
    const float* ld   = (const float*)d_in[7];
    const float* gmma = (const float*)d_in[8];
    const float* beta = (const float*)d_in[9];
    float* out = (float*)d_out;

    k_params<<<1, 256>>>(llr, lim, Btr, Bti, ld);
    k_ln<<<MTOT/8, 256>>>(u, gmma, beta);

    dim3 g1(PDIM/64, MTOT/128);
    k_gemm_bu<<<g1, 256>>>();

    k_scan_ends<<<dim3(NCHUNK, BATCH), 256>>>();
    k_scan_chain<<<BATCH, 256>>>();
    k_scan_write<<<dim3(NCHUNK, BATCH), 256>>>();

    dim3 g2(HDIM/64, MTOT/128);
    k_gemm_out<<<g2, 256>>>(Ctr, Cti, u, out);
}

// round 4
// speedup vs baseline: 1.1856x; 1.1856x over previous
#include <cuda_runtime.h>
#include <cuda_bf16.h>
#include <cstdint>
#include <math.h>

#define BATCH  8
#define LSEQ   4096
#define HDIM   256
#define PDIM   256
#define MTOT   (BATCH*LSEQ)     /* 32768 */
#define CHUNK  64
#define NCHUNK (LSEQ/CHUNK)     /* 64 */
#define KC     512              /* complex-stacked width */

// GEMM tiling
#define BM 128
#define BN 128
#define BKT 32
#define PADROW 80               /* smem row stride bytes: 40 bf16 (32 + 8 pad) */
#define T_AH 0u
#define T_AL 10240u
#define T_BH 20480u
#define T_BL 30720u
#define STAGE_BYTES 40960u
#define SMEM_BYTES (2*STAGE_BYTES)

// ---------------- scratch ---------------------------------------------------
__device__ __align__(1024) __nv_bfloat16 g_hh[MTOT*HDIM];
__device__ __align__(1024) __nv_bfloat16 g_hl[MTOT*HDIM];
__device__ __align__(1024) __nv_bfloat16 g_Wh[KC*HDIM];
__device__ __align__(1024) __nv_bfloat16 g_Wl[KC*HDIM];
__device__ __align__(1024) __nv_bfloat16 g_Ch[HDIM*KC];
__device__ __align__(1024) __nv_bfloat16 g_Cl[HDIM*KC];
__device__ __align__(1024) __nv_bfloat16 g_Xh[(size_t)MTOT*KC];
__device__ __align__(1024) __nv_bfloat16 g_Xl[(size_t)MTOT*KC];
__device__ __align__(1024) float g_bu[(size_t)MTOT*KC];   // real p, imag 256+p
__device__ float g_ar[PDIM];
__device__ float g_ai[PDIM];
__device__ float g_Er[BATCH*NCHUNK*PDIM];
__device__ float g_Ei[BATCH*NCHUNK*PDIM];

// ---------------- PTX helpers (sm_80-class only: valid for .target sm_103) --
__device__ __forceinline__ uint32_t smem_u32(const void* p) {
    uint32_t a;
    asm("{ .reg .u64 t; cvta.to.shared.u64 t, %1; cvt.u32.u64 %0, t; }" : "=r"(a) : "l"(p));
    return a;
}
__device__ __forceinline__ void ldsm4(uint32_t* r, uint32_t addr) {
    asm volatile("ldmatrix.sync.aligned.m8n8.x4.shared.b16 {%0,%1,%2,%3}, [%4];"
        : "=r"(r[0]), "=r"(r[1]), "=r"(r[2]), "=r"(r[3]) : "r"(addr));
}
__device__ __forceinline__ void ldsm2(uint32_t* r, uint32_t addr) {
    asm volatile("ldmatrix.sync.aligned.m8n8.x2.shared.b16 {%0,%1}, [%2];"
        : "=r"(r[0]), "=r"(r[1]) : "r"(addr));
}
__device__ __forceinline__ void mma_bf16(float* c, const uint32_t* a, const uint32_t* b) {
    asm volatile("mma.sync.aligned.m16n8k16.row.col.f32.bf16.bf16.f32 "
        "{%0,%1,%2,%3}, {%4,%5,%6,%7}, {%8,%9}, {%0,%1,%2,%3};"
        : "+f"(c[0]), "+f"(c[1]), "+f"(c[2]), "+f"(c[3])
        : "r"(a[0]), "r"(a[1]), "r"(a[2]), "r"(a[3]), "r"(b[0]), "r"(b[1]));
}
#define CP_COMMIT() asm volatile("cp.async.commit_group;" ::: "memory")
#define CP_WAIT(n)  asm volatile("cp.async.wait_group %0;" :: "n"(n) : "memory")

// ---------------- split helper ----------------------------------------------
__device__ __forceinline__ void bf16_split(float x, __nv_bfloat16& hi, __nv_bfloat16& lo) {
    hi = __float2bfloat16(x);
    lo = __float2bfloat16(x - __bfloat162float(hi));
}

// ---------------- params ----------------------------------------------------
__global__ void k_params(const float* __restrict__ llr, const float* __restrict__ lim,
                         const float* __restrict__ Btr, const float* __restrict__ Bti,
                         const float* __restrict__ Ctr, const float* __restrict__ Cti,
                         const float* __restrict__ ld)
{
    int p = threadIdx.x;
    __shared__ float sgr[PDIM], sgi[PDIM];

    double lr = -exp((double)llr[p]);
    double li = (double)lim[p];
    double d  = exp((double)ld[p]);
    double er = exp(lr * d);
    double ar = er * cos(li * d), ai = er * sin(li * d);
    g_ar[p] = (float)ar;
    g_ai[p] = (float)ai;
    double den = lr*lr + li*li;
    sgr[p] = (float)(((ar - 1.0)*lr + ai*li) / den);
    sgi[p] = (float)((ai*lr - (ar - 1.0)*li) / den);
    __syncthreads();

    // W rows: [0..255] real(B_bar), [256..511] imag(B_bar).  [KC][HDIM]
    for (int idx = p; idx < KC*HDIM; idx += 256) {
        int row = idx >> 8, k = idx & 255;
        int pp = row & 255;
        float br = Btr[pp*HDIM + k], bi = Bti[pp*HDIM + k];
        float w = (row < 256) ? (sgr[pp]*br - sgi[pp]*bi)
                              : (sgr[pp]*bi + sgi[pp]*br);
        __nv_bfloat16 hi, lo; bf16_split(w, hi, lo);
        g_Wh[idx] = hi; g_Wl[idx] = lo;
    }
    // C packed: [HDIM][KC]: cols 0..255 = Cr, 256..511 = -Ci
    for (int idx = p; idx < HDIM*KC; idx += 256) {
        int h = idx >> 9, kk = idx & 511;
        float v = (kk < 256) ? Ctr[h*PDIM + kk] : -Cti[h*PDIM + (kk-256)];
        __nv_bfloat16 hi, lo; bf16_split(v, hi, lo);
        g_Ch[idx] = hi; g_Cl[idx] = lo;
    }
}

// ---------------- LayerNorm -> split bf16 -----------------------------------
__global__ void k_ln(const float* __restrict__ u, const float* __restrict__ gamma,
                     const float* __restrict__ beta)
{
    int warp = threadIdx.x >> 5, lane = threadIdx.x & 31;
    int row  = blockIdx.x * 8 + warp;
    const float* ur = u + (size_t)row * HDIM;

    float v[8]; float sum = 0.f;
#pragma unroll
    for (int j = 0; j < 8; j++) { v[j] = ur[lane + 32*j]; sum += v[j]; }
#pragma unroll
    for (int o = 16; o; o >>= 1) sum += __shfl_xor_sync(0xffffffffu, sum, o);
    float mu = sum * (1.f/HDIM);

    float ss = 0.f;
#pragma unroll
    for (int j = 0; j < 8; j++) { float dd = v[j]-mu; ss += dd*dd; }
#pragma unroll
    for (int o = 16; o; o >>= 1) ss += __shfl_xor_sync(0xffffffffu, ss, o);
    float inv = rsqrtf(ss * (1.f/HDIM) + 1e-5f);

    size_t base = (size_t)row * HDIM;
#pragma unroll
    for (int j = 0; j < 8; j++) {
        int c = lane + 32*j;
        float hv = (v[j]-mu) * inv * __ldg(&gamma[c]) + __ldg(&beta[c]);
        __nv_bfloat16 hi, lo; bf16_split(hv, hi, lo);
        g_hh[base + c] = hi; g_hl[base + c] = lo;
    }
}

// ---------------- async tile loader: 128 rows x 32 bf16 ---------------------
__device__ __forceinline__ void load_tile_async(uint32_t dst_base,
        const __nv_bfloat16* __restrict__ src, int row0, int ldk, int k0, int tid)
{
#pragma unroll
    for (int i = 0; i < 2; i++) {
        int ci = tid + i*256;              // 512 chunks of 16B
        int r = ci >> 2, cc = ci & 3;
        const __nv_bfloat16* g = src + (size_t)(row0 + r)*ldk + k0 + cc*8;
        uint32_t d = dst_base + (uint32_t)(r*PADROW + cc*16);
        asm volatile("cp.async.cg.shared.global [%0], [%1], 16;" :: "r"(d), "l"(g));
    }
}

// ---------------- one BK=32 stage of triple-pass bf16 mma -------------------
__device__ __forceinline__ void compute_stage(uint32_t sbase, int lane,
                                              int m_base, int n_base,
                                              float acc[4][4][4])
{
    int lane16 = lane & 15;
#pragma unroll
    for (int ks = 0; ks < 2; ks++) {
        uint32_t ah[4][4], al[4][4], bh[4][2], bl[4][2];
#pragma unroll
        for (int mi = 0; mi < 4; mi++) {
            uint32_t off = (uint32_t)((m_base + mi*16 + lane16)*PADROW + ks*32 + (lane>>4)*16);
            ldsm4(ah[mi], sbase + T_AH + off);
            ldsm4(al[mi], sbase + T_AL + off);
        }
#pragma unroll
        for (int ni = 0; ni < 4; ni++) {
            uint32_t off = (uint32_t)((n_base + ni*8 + (lane16 & 7))*PADROW + ks*32 + ((lane16>>3)&1)*16);
            ldsm2(bh[ni], sbase + T_BH + off);
            ldsm2(bl[ni], sbase + T_BL + off);
        }
#pragma unroll
        for (int mi = 0; mi < 4; mi++)
#pragma unroll
            for (int ni = 0; ni < 4; ni++) {
                mma_bf16(acc[mi][ni], ah[mi], bh[ni]);
                mma_bf16(acc[mi][ni], ah[mi], bl[ni]);
                mma_bf16(acc[mi][ni], al[mi], bh[ni]);
            }
    }
}

// ---------------- GEMM1: g_bu = [h] @ [W]^T (split 3-pass) ------------------
__global__ __launch_bounds__(256) void k_mgemm1()
{
    extern __shared__ char smem[];
    uint32_t sb = smem_u32(smem);
    int tid = threadIdx.x, wid = tid >> 5, lane = tid & 31;
    int bn = blockIdx.x * BN, bm = blockIdx.y * BM;
    int m_base = (wid & 1) * 64, n_base = (wid >> 1) * 32;

    float acc[4][4][4];
#pragma unroll
    for (int i = 0; i < 4; i++)
#pragma unroll
        for (int j = 0; j < 4; j++)
#pragma unroll
            for (int q = 0; q < 4; q++) acc[i][j][q] = 0.f;

    const int NIT = HDIM / BKT;  // 8
    {   // prologue
        uint32_t s0 = sb;
        load_tile_async(s0 + T_AH, g_hh, bm, HDIM, 0, tid);
        load_tile_async(s0 + T_AL, g_hl, bm, HDIM, 0, tid);
        load_tile_async(s0 + T_BH, g_Wh, bn, HDIM, 0, tid);
        load_tile_async(s0 + T_BL, g_Wl, bn, HDIM, 0, tid);
        CP_COMMIT();
    }
    for (int it = 0; it < NIT; it++) {
        if (it + 1 < NIT) {
            uint32_t s1 = sb + ((it + 1) & 1) * STAGE_BYTES;
            int k0 = (it + 1) * BKT;
            load_tile_async(s1 + T_AH, g_hh, bm, HDIM, k0, tid);
            load_tile_async(s1 + T_AL, g_hl, bm, HDIM, k0, tid);
            load_tile_async(s1 + T_BH, g_Wh, bn, HDIM, k0, tid);
            load_tile_async(s1 + T_BL, g_Wl, bn, HDIM, k0, tid);
            CP_COMMIT();
            CP_WAIT(1);
        } else {
            CP_WAIT(0);
        }
        __syncthreads();
        compute_stage(sb + (it & 1) * STAGE_BYTES, lane, m_base, n_base, acc);
        __syncthreads();
    }

    int r0 = lane >> 2, c0 = (lane & 3) * 2;
#pragma unroll
    for (int mi = 0; mi < 4; mi++) {
        int mg = bm + m_base + mi*16 + r0;
#pragma unroll
        for (int ni = 0; ni < 4; ni++) {
            int cg = bn + n_base + ni*8 + c0;
            *(float2*)&g_bu[(size_t)mg*KC + cg]       = make_float2(acc[mi][ni][0], acc[mi][ni][1]);
            *(float2*)&g_bu[(size_t)(mg+8)*KC + cg]   = make_float2(acc[mi][ni][2], acc[mi][ni][3]);
        }
    }
}

// ---------------- scan phase 1: chunk-end states ----------------------------
__global__ void k_scan_ends()
{
    int p = threadIdx.x;
    int c = blockIdx.x, b = blockIdx.y;
    float ar = g_ar[p], ai = g_ai[p];
    size_t base = ((size_t)b * LSEQ + (size_t)c * CHUNK) * KC;
    float sr = 0.f, si = 0.f;
#pragma unroll 4
    for (int l = 0; l < CHUNK; l++) {
        float xr = g_bu[base + (size_t)l*KC + p];
        float xi = g_bu[base + (size_t)l*KC + 256 + p];
        float nr = fmaf(ar, sr, fmaf(-ai, si, xr));
        float ni = fmaf(ar, si, fmaf( ai, sr, xi));
        sr = nr; si = ni;
    }
    int idx = (b*NCHUNK + c)*PDIM + p;
    g_Er[idx] = sr; g_Ei[idx] = si;
}

// ---------------- scan phase 2: carry chain ---------------------------------
__global__ void k_scan_chain()
{
    int p = threadIdx.x, b = blockIdx.x;
    float ar = g_ar[p], ai = g_ai[p];
    float tr = ar, ti = ai;
#pragma unroll
    for (int i = 0; i < 6; i++) { float nr = tr*tr - ti*ti; ti = 2.f*tr*ti; tr = nr; }
    float sr = 0.f, si = 0.f;
#pragma unroll 8
    for (int c = 0; c < NCHUNK; c++) {
        int idx = (b*NCHUNK + c)*PDIM + p;
        float er = g_Er[idx], ei = g_Ei[idx];
        g_Er[idx] = sr; g_Ei[idx] = si;
        float nr = fmaf(tr, sr, fmaf(-ti, si, er));
        si = fmaf(tr, si, fmaf( ti, sr, ei));
        sr = nr;
    }
}

// ---------------- scan phase 3: rescan, emit split-bf16 X -------------------
__global__ void k_scan_write()
{
    int p = threadIdx.x;
    int c = blockIdx.x, b = blockIdx.y;
    float ar = g_ar[p], ai = g_ai[p];
    int cidx = (b*NCHUNK + c)*PDIM + p;
    float sr = g_Er[cidx], si = g_Ei[cidx];
    size_t base = ((size_t)b * LSEQ + (size_t)c * CHUNK) * KC;
#pragma unroll 4
    for (int l = 0; l < CHUNK; l++) {
        size_t o = base + (size_t)l*KC;
        float xr = g_bu[o + p];
        float xi = g_bu[o + 256 + p];
        float nr = fmaf(ar, sr, fmaf(-ai, si, xr));
        float ni = fmaf(ar, si, fmaf( ai, sr, xi));
        sr = nr; si = ni;
        __nv_bfloat16 hi, lo;
        bf16_split(sr, hi, lo); g_Xh[o + p] = hi;       g_Xl[o + p] = lo;
        bf16_split(si, hi, lo); g_Xh[o + 256 + p] = hi; g_Xl[o + 256 + p] = lo;
    }
}

// ---------------- GEMM2: out = u + gelu(X @ C^T) ----------------------------
__device__ __forceinline__ float gelu_tanh(float x)
{
    float x3 = x*x*x;
    float t = tanhf(0.7978845608028654f * fmaf(0.044715f, x3, x));
    return 0.5f * x * (1.f + t);
}

__global__ __launch_bounds__(256) void k_mgemm2(const float* __restrict__ U,
                                                float* __restrict__ out)
{
    extern __shared__ char smem[];
    uint32_t sb = smem_u32(smem);
    int tid = threadIdx.x, wid = tid >> 5, lane = tid & 31;
    int bn = blockIdx.x * BN, bm = blockIdx.y * BM;
    int m_base = (wid & 1) * 64, n_base = (wid >> 1) * 32;

    float acc[4][4][4];
#pragma unroll
    for (int i = 0; i < 4; i++)
#pragma unroll
        for (int j = 0; j < 4; j++)
#pragma unroll
            for (int q = 0; q < 4; q++) acc[i][j][q] = 0.f;

    const int NIT = KC / BKT;  // 16
    {
        uint32_t s0 = sb;
        load_tile_async(s0 + T_AH, g_Xh, bm, KC, 0, tid);
        load_tile_async(s0 + T_AL, g_Xl, bm, KC, 0, tid);
        load_tile_async(s0 + T_BH, g_Ch, bn, KC, 0, tid);
        load_tile_async(s0 + T_BL, g_Cl, bn, KC, 0, tid);
        CP_COMMIT();
    }
    for (int it = 0; it < NIT; it++) {
        if (it + 1 < NIT) {
            uint32_t s1 = sb + ((it + 1) & 1) * STAGE_BYTES;
            int k0 = (it + 1) * BKT;
            load_tile_async(s1 + T_AH, g_Xh, bm, KC, k0, tid);
            load_tile_async(s1 + T_AL, g_Xl, bm, KC, k0, tid);
            load_tile_async(s1 + T_BH, g_Ch, bn, KC, k0, tid);
            load_tile_async(s1 + T_BL, g_Cl, bn, KC, k0, tid);
            CP_COMMIT();
            CP_WAIT(1);
        } else {
            CP_WAIT(0);
        }
        __syncthreads();
        compute_stage(sb + (it & 1) * STAGE_BYTES, lane, m_base, n_base, acc);
        __syncthreads();
    }

    int r0 = lane >> 2, c0 = (lane & 3) * 2;
#pragma unroll
    for (int mi = 0; mi < 4; mi++) {
        int mg = bm + m_base + mi*16 + r0;
#pragma unroll
        for (int ni = 0; ni < 4; ni++) {
            int cg = bn + n_base + ni*8 + c0;
            {
                size_t o = (size_t)mg*HDIM + cg;
                float2 uv = *(const float2*)&U[o];
                float2 r;
                r.x = uv.x + gelu_tanh(acc[mi][ni][0]);
                r.y = uv.y + gelu_tanh(acc[mi][ni][1]);
                *(float2*)&out[o] = r;
            }
            {
                size_t o = (size_t)(mg+8)*HDIM + cg;
                float2 uv = *(const float2*)&U[o];
                float2 r;
                r.x = uv.x + gelu_tanh(acc[mi][ni][2]);
                r.y = uv.y + gelu_tanh(acc[mi][ni][3]);
                *(float2*)&out[o] = r;
            }
        }
    }
}

// ---------------- launch ----------------------------------------------------
extern "C" void kernel_launch(void* const* d_in, const int* in_sizes, int n_in,
                              void* d_out, int out_size)
{
    const float* u    = (const float*)d_in[0];
    const float* llr  = (const float*)d_in[1];
    const float* lim  = (const float*)d_in[2];
    const float* Btr  = (const float*)d_in[3];
    const float* Bti  = (const float*)d_in[4];
    const float* Ctr  = (const float*)d_in[5];
    const float* Cti  = (const float*)d_in[6];
    const float* ld   = (const float*)d_in[7];
    const float* gmma = (const float*)d_in[8];
    const float* beta = (const float*)d_in[9];
    float* out = (float*)d_out;

    static int inited = 0;
    if (!inited) {
        cudaFuncSetAttribute(k_mgemm1, cudaFuncAttributeMaxDynamicSharedMemorySize, SMEM_BYTES);
        cudaFuncSetAttribute(k_mgemm2, cudaFuncAttributeMaxDynamicSharedMemorySize, SMEM_BYTES);
        inited = 1;
    }

    k_params<<<1, 256>>>(llr, lim, Btr, Bti, Ctr, Cti, ld);
    k_ln<<<MTOT/8, 256>>>(u, gmma, beta);

    k_mgemm1<<<dim3(KC/BN, MTOT/BM), 256, SMEM_BYTES>>>();

    k_scan_ends<<<dim3(NCHUNK, BATCH), 256>>>();
    k_scan_chain<<<BATCH, 256>>>();
    k_scan_write<<<dim3(NCHUNK, BATCH), 256>>>();

    k_mgemm2<<<dim3(HDIM/BN, MTOT/BM), 256, SMEM_BYTES>>>(u, out);
}

// round 5
// speedup vs baseline: 1.5779x; 1.3309x over previous
#include <cuda_runtime.h>
#include <cuda_fp16.h>
#include <cstdint>
#include <math.h>

#define BATCH  8
#define LSEQ   4096
#define HDIM   256
#define PDIM   256
#define MTOT   (BATCH*LSEQ)     /* 32768 */
#define CHUNK  64
#define NCHUNK (LSEQ/CHUNK)     /* 64 */
#define KC     512              /* complex-stacked width */

// GEMM tiling
#define BM 128
#define BN 128
#define BKT 32
#define PADROW 80               /* smem row stride bytes: 40 halves (32 + 8 pad) */
#define T_A 0u
#define T_B 10240u
#define STAGE_BYTES 20480u
#define SMEM_BYTES (2*STAGE_BYTES)   /* 40960 < 48KB default */

#define WSCALE   64.0f
#define WUNSCALE 0.015625f

// ---------------- scratch ---------------------------------------------------
__device__ __align__(1024) __half g_h [MTOT*HDIM];
__device__ __align__(1024) __half g_W [KC*HDIM];
__device__ __align__(1024) __half g_C [HDIM*KC];
__device__ __align__(1024) __half g_X [(size_t)MTOT*KC];
__device__ __align__(1024) float  g_bu[(size_t)MTOT*KC];   // real p, imag 256+p (x WSCALE)
__device__ float g_ar[PDIM];
__device__ float g_ai[PDIM];
__device__ float g_Er[BATCH*NCHUNK*PDIM];
__device__ float g_Ei[BATCH*NCHUNK*PDIM];

// ---------------- PTX helpers (sm_80-class only: valid for .target sm_103) --
__device__ __forceinline__ uint32_t smem_u32(const void* p) {
    uint32_t a;
    asm("{ .reg .u64 t; cvta.to.shared.u64 t, %1; cvt.u32.u64 %0, t; }" : "=r"(a) : "l"(p));
    return a;
}
__device__ __forceinline__ void ldsm4(uint32_t* r, uint32_t addr) {
    asm volatile("ldmatrix.sync.aligned.m8n8.x4.shared.b16 {%0,%1,%2,%3}, [%4];"
        : "=r"(r[0]), "=r"(r[1]), "=r"(r[2]), "=r"(r[3]) : "r"(addr));
}
__device__ __forceinline__ void ldsm2(uint32_t* r, uint32_t addr) {
    asm volatile("ldmatrix.sync.aligned.m8n8.x2.shared.b16 {%0,%1}, [%2];"
        : "=r"(r[0]), "=r"(r[1]) : "r"(addr));
}
__device__ __forceinline__ void mma_f16(float* c, const uint32_t* a, const uint32_t* b) {
    asm volatile("mma.sync.aligned.m16n8k16.row.col.f32.f16.f16.f32 "
        "{%0,%1,%2,%3}, {%4,%5,%6,%7}, {%8,%9}, {%0,%1,%2,%3};"
        : "+f"(c[0]), "+f"(c[1]), "+f"(c[2]), "+f"(c[3])
        : "r"(a[0]), "r"(a[1]), "r"(a[2]), "r"(a[3]), "r"(b[0]), "r"(b[1]));
}
#define CP_COMMIT() asm volatile("cp.async.commit_group;" ::: "memory")
#define CP_WAIT(n)  asm volatile("cp.async.wait_group %0;" :: "n"(n) : "memory")

// ---------------- params ----------------------------------------------------
__global__ void k_params(const float* __restrict__ llr, const float* __restrict__ lim,
                         const float* __restrict__ Btr, const float* __restrict__ Bti,
                         const float* __restrict__ Ctr, const float* __restrict__ Cti,
                         const float* __restrict__ ld)
{
    int p = threadIdx.x;
    __shared__ float sgr[PDIM], sgi[PDIM];

    double lr = -exp((double)llr[p]);
    double li = (double)lim[p];
    double d  = exp((double)ld[p]);
    double er = exp(lr * d);
    double ar = er * cos(li * d), ai = er * sin(li * d);
    g_ar[p] = (float)ar;
    g_ai[p] = (float)ai;
    double den = lr*lr + li*li;
    sgr[p] = (float)(((ar - 1.0)*lr + ai*li) / den);
    sgi[p] = (float)((ai*lr - (ar - 1.0)*li) / den);
    __syncthreads();

    // W rows: [0..255] real(B_bar), [256..511] imag(B_bar).  [KC][HDIM], x WSCALE
    for (int idx = p; idx < KC*HDIM; idx += 256) {
        int row = idx >> 8, k = idx & 255;
        int pp = row & 255;
        float br = Btr[pp*HDIM + k], bi = Bti[pp*HDIM + k];
        float w = (row < 256) ? (sgr[pp]*br - sgi[pp]*bi)
                              : (sgr[pp]*bi + sgi[pp]*br);
        g_W[idx] = __float2half(w * WSCALE);
    }
    // C packed: [HDIM][KC]: cols 0..255 = Cr, 256..511 = -Ci
    for (int idx = p; idx < HDIM*KC; idx += 256) {
        int h = idx >> 9, kk = idx & 511;
        float v = (kk < 256) ? Ctr[h*PDIM + kk] : -Cti[h*PDIM + (kk-256)];
        g_C[idx] = __float2half(v);
    }
}

// ---------------- LayerNorm -> fp16 ------------------------------------------
__global__ void k_ln(const float* __restrict__ u, const float* __restrict__ gamma,
                     const float* __restrict__ beta)
{
    int warp = threadIdx.x >> 5, lane = threadIdx.x & 31;
    int row  = blockIdx.x * 8 + warp;
    const float* ur = u + (size_t)row * HDIM;

    float v[8]; float sum = 0.f;
#pragma unroll
    for (int j = 0; j < 8; j++) { v[j] = ur[lane + 32*j]; sum += v[j]; }
#pragma unroll
    for (int o = 16; o; o >>= 1) sum += __shfl_xor_sync(0xffffffffu, sum, o);
    float mu = sum * (1.f/HDIM);

    float ss = 0.f;
#pragma unroll
    for (int j = 0; j < 8; j++) { float dd = v[j]-mu; ss += dd*dd; }
#pragma unroll
    for (int o = 16; o; o >>= 1) ss += __shfl_xor_sync(0xffffffffu, ss, o);
    float inv = rsqrtf(ss * (1.f/HDIM) + 1e-5f);

    size_t base = (size_t)row * HDIM;
#pragma unroll
    for (int j = 0; j < 8; j++) {
        int c = lane + 32*j;
        g_h[base + c] = __float2half((v[j]-mu) * inv * __ldg(&gamma[c]) + __ldg(&beta[c]));
    }
}

// ---------------- async tile loader: 128 rows x 32 fp16 ----------------------
__device__ __forceinline__ void load_tile_async(uint32_t dst_base,
        const __half* __restrict__ src, int row0, int ldk, int k0, int tid)
{
#pragma unroll
    for (int i = 0; i < 2; i++) {
        int ci = tid + i*256;              // 512 chunks of 16B
        int r = ci >> 2, cc = ci & 3;
        const __half* g = src + (size_t)(row0 + r)*ldk + k0 + cc*8;
        uint32_t d = dst_base + (uint32_t)(r*PADROW + cc*16);
        asm volatile("cp.async.cg.shared.global [%0], [%1], 16;" :: "r"(d), "l"(g));
    }
}

// ---------------- one BK=32 stage: single-pass fp16 mma ----------------------
__device__ __forceinline__ void compute_stage(uint32_t sbase, int lane,
                                              int m_base, int n_base,
                                              float acc[4][4][4])
{
    int lane16 = lane & 15;
#pragma unroll
    for (int ks = 0; ks < 2; ks++) {
        uint32_t a[4][4], b[4][2];
#pragma unroll
        for (int mi = 0; mi < 4; mi++) {
            uint32_t off = (uint32_t)((m_base + mi*16 + lane16)*PADROW + ks*32 + (lane>>4)*16);
            ldsm4(a[mi], sbase + T_A + off);
        }
#pragma unroll
        for (int ni = 0; ni < 4; ni++) {
            uint32_t off = (uint32_t)((n_base + ni*8 + (lane16 & 7))*PADROW + ks*32 + ((lane16>>3)&1)*16);
            ldsm2(b[ni], sbase + T_B + off);
        }
#pragma unroll
        for (int mi = 0; mi < 4; mi++)
#pragma unroll
            for (int ni = 0; ni < 4; ni++)
                mma_f16(acc[mi][ni], a[mi], b[ni]);
    }
}

// ---------------- GEMM1: g_bu = h @ W^T --------------------------------------
__global__ __launch_bounds__(256, 2) void k_mgemm1()
{
    extern __shared__ char smem[];
    uint32_t sb = smem_u32(smem);
    int tid = threadIdx.x, wid = tid >> 5, lane = tid & 31;
    int bn = blockIdx.x * BN, bm = blockIdx.y * BM;
    int m_base = (wid & 1) * 64, n_base = (wid >> 1) * 32;

    float acc[4][4][4];
#pragma unroll
    for (int i = 0; i < 4; i++)
#pragma unroll
        for (int j = 0; j < 4; j++)
#pragma unroll
            for (int q = 0; q < 4; q++) acc[i][j][q] = 0.f;

    const int NIT = HDIM / BKT;  // 8
    load_tile_async(sb + T_A, g_h, bm, HDIM, 0, tid);
    load_tile_async(sb + T_B, g_W, bn, HDIM, 0, tid);
    CP_COMMIT();

    for (int it = 0; it < NIT; it++) {
        if (it + 1 < NIT) {
            uint32_t s1 = sb + ((it + 1) & 1) * STAGE_BYTES;
            int k0 = (it + 1) * BKT;
            load_tile_async(s1 + T_A, g_h, bm, HDIM, k0, tid);
            load_tile_async(s1 + T_B, g_W, bn, HDIM, k0, tid);
            CP_COMMIT();
            CP_WAIT(1);
        } else {
            CP_WAIT(0);
        }
        __syncthreads();
        compute_stage(sb + (it & 1) * STAGE_BYTES, lane, m_base, n_base, acc);
        __syncthreads();
    }

    int r0 = lane >> 2, c0 = (lane & 3) * 2;
#pragma unroll
    for (int mi = 0; mi < 4; mi++) {
        int mg = bm + m_base + mi*16 + r0;
#pragma unroll
        for (int ni = 0; ni < 4; ni++) {
            int cg = bn + n_base + ni*8 + c0;
            *(float2*)&g_bu[(size_t)mg*KC + cg]     = make_float2(acc[mi][ni][0], acc[mi][ni][1]);
            *(float2*)&g_bu[(size_t)(mg+8)*KC + cg] = make_float2(acc[mi][ni][2], acc[mi][ni][3]);
        }
    }
}

// ---------------- scan phase 1: chunk-end states -----------------------------
__global__ void k_scan_ends()
{
    int p = threadIdx.x;
    int c = blockIdx.x, b = blockIdx.y;
    float ar = g_ar[p], ai = g_ai[p];
    size_t base = ((size_t)b * LSEQ + (size_t)c * CHUNK) * KC;
    float sr = 0.f, si = 0.f;
#pragma unroll 4
    for (int l = 0; l < CHUNK; l++) {
        float xr = g_bu[base + (size_t)l*KC + p];
        float xi = g_bu[base + (size_t)l*KC + 256 + p];
        float nr = fmaf(ar, sr, fmaf(-ai, si, xr));
        float ni = fmaf(ar, si, fmaf( ai, sr, xi));
        sr = nr; si = ni;
    }
    int idx = (b*NCHUNK + c)*PDIM + p;
    g_Er[idx] = sr; g_Ei[idx] = si;
}

// ---------------- scan phase 2: carry chain ----------------------------------
__global__ void k_scan_chain()
{
    int p = threadIdx.x, b = blockIdx.x;
    float ar = g_ar[p], ai = g_ai[p];
    float tr = ar, ti = ai;
#pragma unroll
    for (int i = 0; i < 6; i++) { float nr = tr*tr - ti*ti; ti = 2.f*tr*ti; tr = nr; }
    float sr = 0.f, si = 0.f;
#pragma unroll 8
    for (int c = 0; c < NCHUNK; c++) {
        int idx = (b*NCHUNK + c)*PDIM + p;
        float er = g_Er[idx], ei = g_Ei[idx];
        g_Er[idx] = sr; g_Ei[idx] = si;
        float nr = fmaf(tr, sr, fmaf(-ti, si, er));
        si = fmaf(tr, si, fmaf( ti, sr, ei));
        sr = nr;
    }
}

// ---------------- scan phase 3: rescan, emit fp16 X (unscaled) ---------------
__global__ void k_scan_write()
{
    int p = threadIdx.x;
    int c = blockIdx.x, b = blockIdx.y;
    float ar = g_ar[p], ai = g_ai[p];
    int cidx = (b*NCHUNK + c)*PDIM + p;
    float sr = g_Er[cidx], si = g_Ei[cidx];
    size_t base = ((size_t)b * LSEQ + (size_t)c * CHUNK) * KC;
#pragma unroll 4
    for (int l = 0; l < CHUNK; l++) {
        size_t o = base + (size_t)l*KC;
        float xr = g_bu[o + p];
        float xi = g_bu[o + 256 + p];
        float nr = fmaf(ar, sr, fmaf(-ai, si, xr));
        float ni = fmaf(ar, si, fmaf( ai, sr, xi));
        sr = nr; si = ni;
        g_X[o + p]       = __float2half(sr * WUNSCALE);
        g_X[o + 256 + p] = __float2half(si * WUNSCALE);
    }
}

// ---------------- GEMM2: out = u + gelu(X @ C^T) -----------------------------
__device__ __forceinline__ float gelu_tanh(float x)
{
    float x3 = x*x*x;
    float t = tanhf(0.7978845608028654f * fmaf(0.044715f, x3, x));
    return 0.5f * x * (1.f + t);
}

__global__ __launch_bounds__(256, 2) void k_mgemm2(const float* __restrict__ U,
                                                   float* __restrict__ out)
{
    extern __shared__ char smem[];
    uint32_t sb = smem_u32(smem);
    int tid = threadIdx.x, wid = tid >> 5, lane = tid & 31;
    int bn = blockIdx.x * BN, bm = blockIdx.y * BM;
    int m_base = (wid & 1) * 64, n_base = (wid >> 1) * 32;

    float acc[4][4][4];
#pragma unroll
    for (int i = 0; i < 4; i++)
#pragma unroll
        for (int j = 0; j < 4; j++)
#pragma unroll
            for (int q = 0; q < 4; q++) acc[i][j][q] = 0.f;

    const int NIT = KC / BKT;  // 16
    load_tile_async(sb + T_A, g_X, bm, KC, 0, tid);
    load_tile_async(sb + T_B, g_C, bn, KC, 0, tid);
    CP_COMMIT();

    for (int it = 0; it < NIT; it++) {
        if (it + 1 < NIT) {
            uint32_t s1 = sb + ((it + 1) & 1) * STAGE_BYTES;
            int k0 = (it + 1) * BKT;
            load_tile_async(s1 + T_A, g_X, bm, KC, k0, tid);
            load_tile_async(s1 + T_B, g_C, bn, KC, k0, tid);
            CP_COMMIT();
            CP_WAIT(1);
        } else {
            CP_WAIT(0);
        }
        __syncthreads();
        compute_stage(sb + (it & 1) * STAGE_BYTES, lane, m_base, n_base, acc);
        __syncthreads();
    }

    int r0 = lane >> 2, c0 = (lane & 3) * 2;
#pragma unroll
    for (int mi = 0; mi < 4; mi++) {
        int mg = bm + m_base + mi*16 + r0;
#pragma unroll
        for (int ni = 0; ni < 4; ni++) {
            int cg = bn + n_base + ni*8 + c0;
            {
                size_t o = (size_t)mg*HDIM + cg;
                float2 uv = *(const float2*)&U[o];
                float2 r;
                r.x = uv.x + gelu_tanh(acc[mi][ni][0]);
                r.y = uv.y + gelu_tanh(acc[mi][ni][1]);
                *(float2*)&out[o] = r;
            }
            {
                size_t o = (size_t)(mg+8)*HDIM + cg;
                float2 uv = *(const float2*)&U[o];
                float2 r;
                r.x = uv.x + gelu_tanh(acc[mi][ni][2]);
                r.y = uv.y + gelu_tanh(acc[mi][ni][3]);
                *(float2*)&out[o] = r;
            }
        }
    }
}

// ---------------- launch -----------------------------------------------------
extern "C" void kernel_launch(void* const* d_in, const int* in_sizes, int n_in,
                              void* d_out, int out_size)
{
    const float* u    = (const float*)d_in[0];
    const float* llr  = (const float*)d_in[1];
    const float* lim  = (const float*)d_in[2];
    const float* Btr  = (const float*)d_in[3];
    const float* Bti  = (const float*)d_in[4];
    const float* Ctr  = (const float*)d_in[5];
    const float* Cti  = (const float*)d_in[6];
    const float* ld   = (const float*)d_in[7];
    const float* gmma = (const float*)d_in[8];
    const float* beta = (const float*)d_in[9];
    float* out = (float*)d_out;

    k_params<<<1, 256>>>(llr, lim, Btr, Bti, Ctr, Cti, ld);
    k_ln<<<MTOT/8, 256>>>(u, gmma, beta);

    k_mgemm1<<<dim3(KC/BN, MTOT/BM), 256, SMEM_BYTES>>>();

    k_scan_ends<<<dim3(NCHUNK, BATCH), 256>>>();
    k_scan_chain<<<BATCH, 256>>>();
    k_scan_write<<<dim3(NCHUNK, BATCH), 256>>>();

    k_mgemm2<<<dim3(HDIM/BN, MTOT/BM), 256, SMEM_BYTES>>>(u, out);
}

// round 8
// speedup vs baseline: 1.6379x; 1.0380x over previous
#include <cuda_runtime.h>
#include <cuda_fp16.h>
#include <cstdint>
#include <math.h>

#define BATCH  8
#define LSEQ   4096
#define HDIM   256
#define PDIM   256
#define MTOT   (BATCH*LSEQ)     /* 32768 */
#define CHUNK  64
#define NCHUNK (LSEQ/CHUNK)     /* 64 */
#define KC     512              /* complex-stacked width */

// GEMM tiling
#define BM 128
#define BN 128
#define BKT 32
#define PADROW 80               /* smem row stride bytes: 40 halves (32 + 8 pad) */
#define T_A 0u
#define T_B 10240u
#define STAGE_BYTES 20480u
#define NSTAGE 4
#define SMEM_BYTES (NSTAGE*STAGE_BYTES)   /* 81920 */

#define WSCALE   64.0f
#define WUNSCALE 0.015625f

// ---------------- scratch ---------------------------------------------------
__device__ __align__(1024) __half g_h [MTOT*HDIM];
__device__ __align__(1024) __half g_W [KC*HDIM];
__device__ __align__(1024) __half g_C [HDIM*KC];
__device__ __align__(1024) __half g_X [(size_t)MTOT*KC];
__device__ __align__(1024) float  g_bu[(size_t)MTOT*KC];   // real p, imag 256+p (x WSCALE)
__device__ float g_ar[PDIM];
__device__ float g_ai[PDIM];
__device__ float g_Er[BATCH*NCHUNK*PDIM];
__device__ float g_Ei[BATCH*NCHUNK*PDIM];

// ---------------- PTX helpers (sm_80-class only: valid for .target sm_103) --
__device__ __forceinline__ uint32_t smem_u32(const void* p) {
    uint32_t a;
    asm("{ .reg .u64 t; cvta.to.shared.u64 t, %1; cvt.u32.u64 %0, t; }" : "=r"(a) : "l"(p));
    return a;
}
__device__ __forceinline__ void ldsm4(uint32_t* r, uint32_t addr) {
    asm volatile("ldmatrix.sync.aligned.m8n8.x4.shared.b16 {%0,%1,%2,%3}, [%4];"
        : "=r"(r[0]), "=r"(r[1]), "=r"(r[2]), "=r"(r[3]) : "r"(addr));
}
__device__ __forceinline__ void mma_f16(float* c, const uint32_t* a, const uint32_t* b) {
    asm volatile("mma.sync.aligned.m16n8k16.row.col.f32.f16.f16.f32 "
        "{%0,%1,%2,%3}, {%4,%5,%6,%7}, {%8,%9}, {%0,%1,%2,%3};"
        : "+f"(c[0]), "+f"(c[1]), "+f"(c[2]), "+f"(c[3])
        : "r"(a[0]), "r"(a[1]), "r"(a[2]), "r"(a[3]), "r"(b[0]), "r"(b[1]));
}
__device__ __forceinline__ float tanh_fast(float x) {
    float r; asm("tanh.approx.f32 %0, %1;" : "=f"(r) : "f"(x)); return r;
}
#define CP_COMMIT() asm volatile("cp.async.commit_group;" ::: "memory")
#define CP_WAIT(n)  asm volatile("cp.async.wait_group %0;" :: "n"(n) : "memory")

// ---------------- params ----------------------------------------------------
__global__ void k_params(const float* __restrict__ llr, const float* __restrict__ lim,
                         const float* __restrict__ Btr, const float* __restrict__ Bti,
                         const float* __restrict__ Ctr, const float* __restrict__ Cti,
                         const float* __restrict__ ld)
{
    int p = threadIdx.x;
    __shared__ float sgr[PDIM], sgi[PDIM];

    double lr = -exp((double)llr[p]);
    double li = (double)lim[p];
    double d  = exp((double)ld[p]);
    double er = exp(lr * d);
    double ar = er * cos(li * d), ai = er * sin(li * d);
    g_ar[p] = (float)ar;
    g_ai[p] = (float)ai;
    double den = lr*lr + li*li;
    sgr[p] = (float)(((ar - 1.0)*lr + ai*li) / den);
    sgi[p] = (float)((ai*lr - (ar - 1.0)*li) / den);
    __syncthreads();

    // W rows: [0..255] real(B_bar), [256..511] imag(B_bar).  [KC][HDIM], x WSCALE
    for (int idx = p; idx < KC*HDIM; idx += 256) {
        int row = idx >> 8, k = idx & 255;
        int pp = row & 255;
        float br = Btr[pp*HDIM + k], bi = Bti[pp*HDIM + k];
        float w = (row < 256) ? (sgr[pp]*br - sgi[pp]*bi)
                              : (sgr[pp]*bi + sgi[pp]*br);
        g_W[idx] = __float2half(w * WSCALE);
    }
    // C packed: [HDIM][KC]: cols 0..255 = Cr, 256..511 = -Ci
    for (int idx = p; idx < HDIM*KC; idx += 256) {
        int h = idx >> 9, kk = idx & 511;
        float v = (kk < 256) ? Ctr[h*PDIM + kk] : -Cti[h*PDIM + (kk-256)];
        g_C[idx] = __float2half(v);
    }
}

// ---------------- LayerNorm -> fp16 ------------------------------------------
__global__ void k_ln(const float* __restrict__ u, const float* __restrict__ gamma,
                     const float* __restrict__ beta)
{
    int warp = threadIdx.x >> 5, lane = threadIdx.x & 31;
    int row  = blockIdx.x * 8 + warp;
    const float* ur = u + (size_t)row * HDIM;

    float v[8]; float sum = 0.f;
#pragma unroll
    for (int j = 0; j < 8; j++) { v[j] = ur[lane + 32*j]; sum += v[j]; }
#pragma unroll
    for (int o = 16; o; o >>= 1) sum += __shfl_xor_sync(0xffffffffu, sum, o);
    float mu = sum * (1.f/HDIM);

    float ss = 0.f;
#pragma unroll
    for (int j = 0; j < 8; j++) { float dd = v[j]-mu; ss += dd*dd; }
#pragma unroll
    for (int o = 16; o; o >>= 1) ss += __shfl_xor_sync(0xffffffffu, ss, o);
    float inv = rsqrtf(ss * (1.f/HDIM) + 1e-5f);

    size_t base = (size_t)row * HDIM;
#pragma unroll
    for (int j = 0; j < 8; j++) {
        int c = lane + 32*j;
        g_h[base + c] = __float2half((v[j]-mu) * inv * __ldg(&gamma[c]) + __ldg(&beta[c]));
    }
}

// ---------------- async tile loader: 128 rows x 32 fp16 ----------------------
__device__ __forceinline__ void load_tile_async(uint32_t dst_base,
        const __half* __restrict__ src, int row0, int ldk, int k0, int tid)
{
#pragma unroll
    for (int i = 0; i < 2; i++) {
        int ci = tid + i*256;              // 512 chunks of 16B
        int r = ci >> 2, cc = ci & 3;
        const __half* g = src + (size_t)(row0 + r)*ldk + k0 + cc*8;
        uint32_t d = dst_base + (uint32_t)(r*PADROW + cc*16);
        asm volatile("cp.async.cg.shared.global [%0], [%1], 16;" :: "r"(d), "l"(g));
    }
}

// ---------------- one BK=32 stage: single-pass fp16 mma ----------------------
__device__ __forceinline__ void compute_stage(uint32_t sbase, int lane,
                                              int m_base, int n_base,
                                              float acc[4][4][4])
{
    int lane16 = lane & 15;
#pragma unroll
    for (int ks = 0; ks < 2; ks++) {
        uint32_t a[4][4], b[8];
#pragma unroll
        for (int mi = 0; mi < 4; mi++) {
            uint32_t off = (uint32_t)((m_base + mi*16 + lane16)*PADROW + ks*32 + (lane>>4)*16);
            ldsm4(a[mi], sbase + T_A + off);
        }
#pragma unroll
        for (int nn = 0; nn < 4; nn += 2) {
            uint32_t off = (uint32_t)((n_base + (nn + (lane>>4))*8 + (lane & 7))*PADROW
                                      + ks*32 + ((lane>>3)&1)*16);
            ldsm4(&b[nn*2], sbase + T_B + off);
        }
#pragma unroll
        for (int mi = 0; mi < 4; mi++)
#pragma unroll
            for (int ni = 0; ni < 4; ni++)
                mma_f16(acc[mi][ni], a[mi], &b[ni*2]);
    }
}

// ---------------- 4-stage mainloop (1 sync/iter) ------------------------------
__device__ __forceinline__ void gemm_mainloop(uint32_t sb, int tid, int lane,
        int m_base, int n_base, int bm, int bn,
        const __half* __restrict__ A, const __half* __restrict__ B,
        int ldk, int NIT, float acc[4][4][4])
{
#pragma unroll
    for (int s = 0; s < NSTAGE-1; s++) {
        uint32_t ss = sb + s * STAGE_BYTES;
        load_tile_async(ss + T_A, A, bm, ldk, s*BKT, tid);
        load_tile_async(ss + T_B, B, bn, ldk, s*BKT, tid);
        CP_COMMIT();
    }
    for (int it = 0; it < NIT; it++) {
        CP_WAIT(NSTAGE-2);
        __syncthreads();
        int pre = it + NSTAGE - 1;
        if (pre < NIT) {
            uint32_t ss = sb + (pre & (NSTAGE-1)) * STAGE_BYTES;
            load_tile_async(ss + T_A, A, bm, ldk, pre*BKT, tid);
            load_tile_async(ss + T_B, B, bn, ldk, pre*BKT, tid);
        }
        CP_COMMIT();
        compute_stage(sb + (it & (NSTAGE-1)) * STAGE_BYTES, lane, m_base, n_base, acc);
    }
}

// ---------------- GEMM1: g_bu = h @ W^T --------------------------------------
__global__ __launch_bounds__(256, 2) void k_mgemm1()
{
    extern __shared__ char smem[];
    uint32_t sb = smem_u32(smem);
    int tid = threadIdx.x, wid = tid >> 5, lane = tid & 31;
    int bn = blockIdx.x * BN, bm = blockIdx.y * BM;
    int m_base = (wid & 1) * 64, n_base = (wid >> 1) * 32;

    float acc[4][4][4];
#pragma unroll
    for (int i = 0; i < 4; i++)
#pragma unroll
        for (int j = 0; j < 4; j++)
#pragma unroll
            for (int q = 0; q < 4; q++) acc[i][j][q] = 0.f;

    gemm_mainloop(sb, tid, lane, m_base, n_base, bm, bn, g_h, g_W, HDIM, HDIM/BKT, acc);

    int r0 = lane >> 2, c0 = (lane & 3) * 2;
#pragma unroll
    for (int mi = 0; mi < 4; mi++) {
        int mg = bm + m_base + mi*16 + r0;
#pragma unroll
        for (int ni = 0; ni < 4; ni++) {
            int cg = bn + n_base + ni*8 + c0;
            *(float2*)&g_bu[(size_t)mg*KC + cg]     = make_float2(acc[mi][ni][0], acc[mi][ni][1]);
            *(float2*)&g_bu[(size_t)(mg+8)*KC + cg] = make_float2(acc[mi][ni][2], acc[mi][ni][3]);
        }
    }
}

// ---------------- scan phase 1: chunk-end states (128t, float2 lanes) --------
__global__ void k_scan_ends()
{
    int t = threadIdx.x;                 // 0..127, handles states 2t, 2t+1
    int c = blockIdx.x, b = blockIdx.y;
    int pr = 2*t;
    float2 ar = *(const float2*)&g_ar[pr];
    float2 ai = *(const float2*)&g_ai[pr];
    size_t base = ((size_t)b * LSEQ + (size_t)c * CHUNK) * KC;
    float2 sr = make_float2(0.f, 0.f), si = make_float2(0.f, 0.f);
#pragma unroll 4
    for (int l = 0; l < CHUNK; l++) {
        float2 xr = *(const float2*)&g_bu[base + (size_t)l*KC + pr];
        float2 xi = *(const float2*)&g_bu[base + (size_t)l*KC + 256 + pr];
        float nrx = fmaf(ar.x, sr.x, fmaf(-ai.x, si.x, xr.x));
        float nix = fmaf(ar.x, si.x, fmaf( ai.x, sr.x, xi.x));
        float nry = fmaf(ar.y, sr.y, fmaf(-ai.y, si.y, xr.y));
        float niy = fmaf(ar.y, si.y, fmaf( ai.y, sr.y, xi.y));
        sr.x = nrx; si.x = nix; sr.y = nry; si.y = niy;
    }
    int idx = (b*NCHUNK + c)*PDIM + pr;
    *(float2*)&g_Er[idx] = sr;
    *(float2*)&g_Ei[idx] = si;
}

// ---------------- scan phase 2: carry chain ----------------------------------
__global__ void k_scan_chain()
{
    int p = threadIdx.x, b = blockIdx.x;
    float ar = g_ar[p], ai = g_ai[p];
    float tr = ar, ti = ai;
#pragma unroll
    for (int i = 0; i < 6; i++) { float nr = tr*tr - ti*ti; ti = 2.f*tr*ti; tr = nr; }
    float sr = 0.f, si = 0.f;
#pragma unroll 8
    for (int c = 0; c < NCHUNK; c++) {
        int idx = (b*NCHUNK + c)*PDIM + p;
        float er = g_Er[idx], ei = g_Ei[idx];
        g_Er[idx] = sr; g_Ei[idx] = si;
        float nr = fmaf(tr, sr, fmaf(-ti, si, er));
        si = fmaf(tr, si, fmaf( ti, sr, ei));
        sr = nr;
    }
}

// ---------------- scan phase 3: rescan, emit fp16 X (128t, float2 lanes) -----
__global__ void k_scan_write()
{
    int t = threadIdx.x;
    int c = blockIdx.x, b = blockIdx.y;
    int pr = 2*t;
    float2 ar = *(const float2*)&g_ar[pr];
    float2 ai = *(const float2*)&g_ai[pr];
    int cidx = (b*NCHUNK + c)*PDIM + pr;
    float2 sr = *(const float2*)&g_Er[cidx];
    float2 si = *(const float2*)&g_Ei[cidx];
    size_t base = ((size_t)b * LSEQ + (size_t)c * CHUNK) * KC;
#pragma unroll 4
    for (int l = 0; l < CHUNK; l++) {
        size_t o = base + (size_t)l*KC;
        float2 xr = *(const float2*)&g_bu[o + pr];
        float2 xi = *(const float2*)&g_bu[o + 256 + pr];
        float nrx = fmaf(ar.x, sr.x, fmaf(-ai.x, si.x, xr.x));
        float nix = fmaf(ar.x, si.x, fmaf( ai.x, sr.x, xi.x));
        float nry = fmaf(ar.y, sr.y, fmaf(-ai.y, si.y, xr.y));
        float niy = fmaf(ar.y, si.y, fmaf( ai.y, sr.y, xi.y));
        sr.x = nrx; si.x = nix; sr.y = nry; si.y = niy;
        *(__half2*)&g_X[o + pr]       = __floats2half2_rn(sr.x*WUNSCALE, sr.y*WUNSCALE);
        *(__half2*)&g_X[o + 256 + pr] = __floats2half2_rn(si.x*WUNSCALE, si.y*WUNSCALE);
    }
}

// ---------------- GEMM2: out = u + gelu(X @ C^T) -----------------------------
__device__ __forceinline__ float gelu_tanh(float x)
{
    float x3 = x*x*x;
    float t = tanh_fast(0.7978845608028654f * fmaf(0.044715f, x3, x));
    return 0.5f * x * (1.f + t);
}

__global__ __launch_bounds__(256, 2) void k_mgemm2(const float* __restrict__ U,
                                                   float* __restrict__ out)
{
    extern __shared__ char smem[];
    uint32_t sb = smem_u32(smem);
    int tid = threadIdx.x, wid = tid >> 5, lane = tid & 31;
    int bn = blockIdx.x * BN, bm = blockIdx.y * BM;
    int m_base = (wid & 1) * 64, n_base = (wid >> 1) * 32;

    float acc[4][4][4];
#pragma unroll
    for (int i = 0; i < 4; i++)
#pragma unroll
        for (int j = 0; j < 4; j++)
#pragma unroll
            for (int q = 0; q < 4; q++) acc[i][j][q] = 0.f;

    gemm_mainloop(sb, tid, lane, m_base, n_base, bm, bn, g_X, g_C, KC, KC/BKT, acc);

    int r0 = lane >> 2, c0 = (lane & 3) * 2;
#pragma unroll
    for (int mi = 0; mi < 4; mi++) {
        int mg = bm + m_base + mi*16 + r0;
#pragma unroll
        for (int ni = 0; ni < 4; ni++) {
            int cg = bn + n_base + ni*8 + c0;
            {
                size_t o = (size_t)mg*HDIM + cg;
                float2 uv = *(const float2*)&U[o];
                float2 r;
                r.x = uv.x + gelu_tanh(acc[mi][ni][0]);
                r.y = uv.y + gelu_tanh(acc[mi][ni][1]);
                *(float2*)&out[o] = r;
            }
            {
                size_t o = (size_t)(mg+8)*HDIM + cg;
                float2 uv = *(const float2*)&U[o];
                float2 r;
                r.x = uv.x + gelu_tanh(acc[mi][ni][2]);
                r.y = uv.y + gelu_tanh(acc[mi][ni][3]);
                *(float2*)&out[o] = r;
            }
        }
    }
}

// ---------------- launch -----------------------------------------------------
extern "C" void kernel_launch(void* const* d_in, const int* in_sizes, int n_in,
                              void* d_out, int out_size)
{
    const float* u    = (const float*)d_in[0];
    const float* llr  = (const float*)d_in[1];
    const float* lim  = (const float*)d_in[2];
    const float* Btr  = (const float*)d_in[3];
    const float* Bti  = (const float*)d_in[4];
    const float* Ctr  = (const float*)d_in[5];
    const float* Cti  = (const float*)d_in[6];
    const float* ld   = (const float*)d_in[7];
    const float* gmma = (const float*)d_in[8];
    const float* beta = (const float*)d_in[9];
    float* out = (float*)d_out;

    cudaFuncSetAttribute(k_mgemm1, cudaFuncAttributeMaxDynamicSharedMemorySize, SMEM_BYTES);
    cudaFuncSetAttribute(k_mgemm2, cudaFuncAttributeMaxDynamicSharedMemorySize, SMEM_BYTES);

    k_params<<<1, 256>>>(llr, lim, Btr, Bti, Ctr, Cti, ld);
    k_ln<<<MTOT/8, 256>>>(u, gmma, beta);

    k_mgemm1<<<dim3(KC/BN, MTOT/BM), 256, SMEM_BYTES>>>();

    k_scan_ends<<<dim3(NCHUNK, BATCH), 128>>>();
    k_scan_chain<<<BATCH, 256>>>();
    k_scan_write<<<dim3(NCHUNK, BATCH), 128>>>();

    k_mgemm2<<<dim3(HDIM/BN, MTOT/BM), 256, SMEM_BYTES>>>(u, out);
}

// round 12
// speedup vs baseline: 3.9347x; 2.4023x over previous
#include <cuda_runtime.h>
#include <cuda_fp16.h>
#include <cstdint>
#include <math.h>

#define BATCH  8
#define LSEQ   4096
#define HDIM   256
#define PDIM   256
#define MTOT   (BATCH*LSEQ)     /* 32768 */
#define CHUNK  64
#define NCHUNK (LSEQ/CHUNK)     /* 64 */
#define KC     512              /* complex-stacked width */

// GEMM tiling
#define BM 128
#define BN 128
#define BKT 32
#define PADROW 80               /* smem row stride bytes: 40 halves (32 + 8 pad) */
#define T_A 0u
#define T_B 10240u
#define STAGE_BYTES 20480u
#define NSTAGE 4
#define SMEM_BYTES (NSTAGE*STAGE_BYTES)   /* 81920 */

#define WSCALE   64.0f
#define WUNSCALE 0.015625f

// ---------------- scratch ---------------------------------------------------
__device__ __align__(1024) __half g_h [MTOT*HDIM];
__device__ __align__(1024) __half g_W [KC*HDIM];
__device__ __align__(1024) __half g_C [HDIM*KC];
__device__ __align__(1024) __half g_X [(size_t)MTOT*KC];
__device__ __align__(1024) __half g_bu[(size_t)MTOT*KC];   // fp16, x WSCALE
__device__ float g_ar[PDIM];
__device__ float g_ai[PDIM];
__device__ float g_gr[PDIM];
__device__ float g_gi[PDIM];
__device__ float g_Er[BATCH*NCHUNK*PDIM];
__device__ float g_Ei[BATCH*NCHUNK*PDIM];

// ---------------- PTX helpers (sm_80-class only: valid for .target sm_103) --
__device__ __forceinline__ uint32_t smem_u32(const void* p) {
    uint32_t a;
    asm("{ .reg .u64 t; cvta.to.shared.u64 t, %1; cvt.u32.u64 %0, t; }" : "=r"(a) : "l"(p));
    return a;
}
__device__ __forceinline__ void ldsm4(uint32_t* r, uint32_t addr) {
    asm volatile("ldmatrix.sync.aligned.m8n8.x4.shared.b16 {%0,%1,%2,%3}, [%4];"
        : "=r"(r[0]), "=r"(r[1]), "=r"(r[2]), "=r"(r[3]) : "r"(addr));
}
__device__ __forceinline__ void mma_f16(float* c, const uint32_t* a, const uint32_t* b) {
    asm volatile("mma.sync.aligned.m16n8k16.row.col.f32.f16.f16.f32 "
        "{%0,%1,%2,%3}, {%4,%5,%6,%7}, {%8,%9}, {%0,%1,%2,%3};"
        : "+f"(c[0]), "+f"(c[1]), "+f"(c[2]), "+f"(c[3])
        : "r"(a[0]), "r"(a[1]), "r"(a[2]), "r"(a[3]), "r"(b[0]), "r"(b[1]));
}
__device__ __forceinline__ float tanh_fast(float x) {
    float r; asm("tanh.approx.f32 %0, %1;" : "=f"(r) : "f"(x)); return r;
}
#define CP_COMMIT() asm volatile("cp.async.commit_group;" ::: "memory")
#define CP_WAIT(n)  asm volatile("cp.async.wait_group %0;" :: "n"(n) : "memory")

// ---------------- params: lambda_bar + gains only (1 block) ------------------
__global__ void k_params(const float* __restrict__ llr, const float* __restrict__ lim,
                         const float* __restrict__ ld)
{
    int p = threadIdx.x;
    double lr = -exp((double)llr[p]);
    double li = (double)lim[p];
    double d  = exp((double)ld[p]);
    double er = exp(lr * d);
    double ar = er * cos(li * d), ai = er * sin(li * d);
    g_ar[p] = (float)ar;
    g_ai[p] = (float)ai;
    double den = lr*lr + li*li;
    g_gr[p] = (float)(((ar - 1.0)*lr + ai*li) / den);
    g_gi[p] = (float)((ai*lr - (ar - 1.0)*li) / den);
}

// ---------------- parallel W/C fill (512 blocks) -----------------------------
__global__ void k_fill(const float* __restrict__ Btr, const float* __restrict__ Bti,
                       const float* __restrict__ Ctr, const float* __restrict__ Cti)
{
    int idx = blockIdx.x * 256 + threadIdx.x;       // 0 .. 131071
    // W rows: [0..255] real(B_bar), [256..511] imag(B_bar).  [KC][HDIM], x WSCALE
    {
        int row = idx >> 8, k = idx & 255, pp = row & 255;
        float gr = g_gr[pp], gi = g_gi[pp];
        float br = Btr[pp*HDIM + k], bi = Bti[pp*HDIM + k];
        float w = (row < 256) ? (gr*br - gi*bi) : (gr*bi + gi*br);
        g_W[idx] = __float2half(w * WSCALE);
    }
    // C packed: [HDIM][KC]: cols 0..255 = Cr, 256..511 = -Ci
    {
        int h = idx >> 9, kk = idx & 511;
        float v = (kk < 256) ? Ctr[h*PDIM + kk] : -Cti[h*PDIM + (kk-256)];
        g_C[idx] = __float2half(v);
    }
}

// ---------------- LayerNorm -> fp16 ------------------------------------------
__global__ void k_ln(const float* __restrict__ u, const float* __restrict__ gamma,
                     const float* __restrict__ beta)
{
    int warp = threadIdx.x >> 5, lane = threadIdx.x & 31;
    int row  = blockIdx.x * 8 + warp;
    const float* ur = u + (size_t)row * HDIM;

    float v[8]; float sum = 0.f;
#pragma unroll
    for (int j = 0; j < 8; j++) { v[j] = ur[lane + 32*j]; sum += v[j]; }
#pragma unroll
    for (int o = 16; o; o >>= 1) sum += __shfl_xor_sync(0xffffffffu, sum, o);
    float mu = sum * (1.f/HDIM);

    float ss = 0.f;
#pragma unroll
    for (int j = 0; j < 8; j++) { float dd = v[j]-mu; ss += dd*dd; }
#pragma unroll
    for (int o = 16; o; o >>= 1) ss += __shfl_xor_sync(0xffffffffu, ss, o);
    float inv = rsqrtf(ss * (1.f/HDIM) + 1e-5f);

    size_t base = (size_t)row * HDIM;
#pragma unroll
    for (int j = 0; j < 8; j++) {
        int c = lane + 32*j;
        g_h[base + c] = __float2half((v[j]-mu) * inv * __ldg(&gamma[c]) + __ldg(&beta[c]));
    }
}

// ---------------- async tile loader: 128 rows x 32 fp16 ----------------------
__device__ __forceinline__ void load_tile_async(uint32_t dst_base,
        const __half* __restrict__ src, int row0, int ldk, int k0, int tid)
{
#pragma unroll
    for (int i = 0; i < 2; i++) {
        int ci = tid + i*256;              // 512 chunks of 16B
        int r = ci >> 2, cc = ci & 3;
        const __half* g = src + (size_t)(row0 + r)*ldk + k0 + cc*8;
        uint32_t d = dst_base + (uint32_t)(r*PADROW + cc*16);
        asm volatile("cp.async.cg.shared.global [%0], [%1], 16;" :: "r"(d), "l"(g));
    }
}

// ---------------- one BK=32 stage: single-pass fp16 mma ----------------------
__device__ __forceinline__ void compute_stage(uint32_t sbase, int lane,
                                              int m_base, int n_base,
                                              float acc[4][4][4])
{
    int lane16 = lane & 15;
#pragma unroll
    for (int ks = 0; ks < 2; ks++) {
        uint32_t a[4][4], b[8];
#pragma unroll
        for (int mi = 0; mi < 4; mi++) {
            uint32_t off = (uint32_t)((m_base + mi*16 + lane16)*PADROW + ks*32 + (lane>>4)*16);
            ldsm4(a[mi], sbase + T_A + off);
        }
#pragma unroll
        for (int nn = 0; nn < 4; nn += 2) {
            uint32_t off = (uint32_t)((n_base + (nn + (lane>>4))*8 + (lane & 7))*PADROW
                                      + ks*32 + ((lane>>3)&1)*16);
            ldsm4(&b[nn*2], sbase + T_B + off);
        }
#pragma unroll
        for (int mi = 0; mi < 4; mi++)
#pragma unroll
            for (int ni = 0; ni < 4; ni++)
                mma_f16(acc[mi][ni], a[mi], &b[ni*2]);
    }
}

// ---------------- 4-stage mainloop (1 sync/iter) ------------------------------
__device__ __forceinline__ void gemm_mainloop(uint32_t sb, int tid, int lane,
        int m_base, int n_base, int bm, int bn,
        const __half* __restrict__ A, const __half* __restrict__ B,
        int ldk, int NIT, float acc[4][4][4])
{
#pragma unroll
    for (int s = 0; s < NSTAGE-1; s++) {
        uint32_t ss = sb + s * STAGE_BYTES;
        load_tile_async(ss + T_A, A, bm, ldk, s*BKT, tid);
        load_tile_async(ss + T_B, B, bn, ldk, s*BKT, tid);
        CP_COMMIT();
    }
    for (int it = 0; it < NIT; it++) {
        CP_WAIT(NSTAGE-2);
        __syncthreads();
        int pre = it + NSTAGE - 1;
        if (pre < NIT) {
            uint32_t ss = sb + (pre & (NSTAGE-1)) * STAGE_BYTES;
            load_tile_async(ss + T_A, A, bm, ldk, pre*BKT, tid);
            load_tile_async(ss + T_B, B, bn, ldk, pre*BKT, tid);
        }
        CP_COMMIT();
        compute_stage(sb + (it & (NSTAGE-1)) * STAGE_BYTES, lane, m_base, n_base, acc);
    }
}

// ---------------- GEMM1: g_bu = h @ W^T (fp16 out) ---------------------------
__global__ __launch_bounds__(256, 2) void k_mgemm1()
{
    extern __shared__ char smem[];
    uint32_t sb = smem_u32(smem);
    int tid = threadIdx.x, wid = tid >> 5, lane = tid & 31;
    int bn = blockIdx.x * BN, bm = blockIdx.y * BM;
    int m_base = (wid & 1) * 64, n_base = (wid >> 1) * 32;

    float acc[4][4][4];
#pragma unroll
    for (int i = 0; i < 4; i++)
#pragma unroll
        for (int j = 0; j < 4; j++)
#pragma unroll
            for (int q = 0; q < 4; q++) acc[i][j][q] = 0.f;

    gemm_mainloop(sb, tid, lane, m_base, n_base, bm, bn, g_h, g_W, HDIM, HDIM/BKT, acc);

    int r0 = lane >> 2, c0 = (lane & 3) * 2;
#pragma unroll
    for (int mi = 0; mi < 4; mi++) {
        int mg = bm + m_base + mi*16 + r0;
#pragma unroll
        for (int ni = 0; ni < 4; ni++) {
            int cg = bn + n_base + ni*8 + c0;
            *(__half2*)&g_bu[(size_t)mg*KC + cg]     = __floats2half2_rn(acc[mi][ni][0], acc[mi][ni][1]);
            *(__half2*)&g_bu[(size_t)(mg+8)*KC + cg] = __floats2half2_rn(acc[mi][ni][2], acc[mi][ni][3]);
        }
    }
}

// ---------------- scan phase 1: chunk-end states (256t, 2 chunks/block) ------
__global__ void k_scan_ends()
{
    int tt = threadIdx.x;
    int c  = blockIdx.x * 2 + (tt >> 7);
    int t  = tt & 127;
    int b  = blockIdx.y;
    int pr = 2*t;
    float2 ar = *(const float2*)&g_ar[pr];
    float2 ai = *(const float2*)&g_ai[pr];
    size_t base = ((size_t)b * LSEQ + (size_t)c * CHUNK) * KC;
    float2 sr = make_float2(0.f, 0.f), si = make_float2(0.f, 0.f);
#pragma unroll 4
    for (int l = 0; l < CHUNK; l++) {
        float2 xr = __half22float2(*(const __half2*)&g_bu[base + (size_t)l*KC + pr]);
        float2 xi = __half22float2(*(const __half2*)&g_bu[base + (size_t)l*KC + 256 + pr]);
        float nrx = fmaf(ar.x, sr.x, fmaf(-ai.x, si.x, xr.x));
        float nix = fmaf(ar.x, si.x, fmaf( ai.x, sr.x, xi.x));
        float nry = fmaf(ar.y, sr.y, fmaf(-ai.y, si.y, xr.y));
        float niy = fmaf(ar.y, si.y, fmaf( ai.y, sr.y, xi.y));
        sr.x = nrx; si.x = nix; sr.y = nry; si.y = niy;
    }
    int idx = (b*NCHUNK + c)*PDIM + pr;
    *(float2*)&g_Er[idx] = sr;
    *(float2*)&g_Ei[idx] = si;
}

// ---------------- scan phase 2: carry chain ----------------------------------
__global__ void k_scan_chain()
{
    int p = threadIdx.x, b = blockIdx.x;
    float ar = g_ar[p], ai = g_ai[p];
    float tr = ar, ti = ai;
#pragma unroll
    for (int i = 0; i < 6; i++) { float nr = tr*tr - ti*ti; ti = 2.f*tr*ti; tr = nr; }
    float sr = 0.f, si = 0.f;
#pragma unroll 8
    for (int c = 0; c < NCHUNK; c++) {
        int idx = (b*NCHUNK + c)*PDIM + p;
        float er = g_Er[idx], ei = g_Ei[idx];
        g_Er[idx] = sr; g_Ei[idx] = si;
        float nr = fmaf(tr, sr, fmaf(-ti, si, er));
        si = fmaf(tr, si, fmaf( ti, sr, ei));
        sr = nr;
    }
}

// ---------------- scan phase 3: rescan, emit fp16 X --------------------------
__global__ void k_scan_write()
{
    int tt = threadIdx.x;
    int c  = blockIdx.x * 2 + (tt >> 7);
    int t  = tt & 127;
    int b  = blockIdx.y;
    int pr = 2*t;
    float2 ar = *(const float2*)&g_ar[pr];
    float2 ai = *(const float2*)&g_ai[pr];
    int cidx = (b*NCHUNK + c)*PDIM + pr;
    float2 sr = *(const float2*)&g_Er[cidx];
    float2 si = *(const float2*)&g_Ei[cidx];
    size_t base = ((size_t)b * LSEQ + (size_t)c * CHUNK) * KC;
#pragma unroll 4
    for (int l = 0; l < CHUNK; l++) {
        size_t o = base + (size_t)l*KC;
        float2 xr = __half22float2(*(const __half2*)&g_bu[o + pr]);
        float2 xi = __half22float2(*(const __half2*)&g_bu[o + 256 + pr]);
        float nrx = fmaf(ar.x, sr.x, fmaf(-ai.x, si.x, xr.x));
        float nix = fmaf(ar.x, si.x, fmaf( ai.x, sr.x, xi.x));
        float nry = fmaf(ar.y, sr.y, fmaf(-ai.y, si.y, xr.y));
        float niy = fmaf(ar.y, si.y, fmaf( ai.y, sr.y, xi.y));
        sr.x = nrx; si.x = nix; sr.y = nry; si.y = niy;
        *(__half2*)&g_X[o + pr]       = __floats2half2_rn(sr.x*WUNSCALE, sr.y*WUNSCALE);
        *(__half2*)&g_X[o + 256 + pr] = __floats2half2_rn(si.x*WUNSCALE, si.y*WUNSCALE);
    }
}

// ---------------- GEMM2: out = u + gelu(X @ C^T) -----------------------------
__device__ __forceinline__ float gelu_tanh(float x)
{
    float x3 = x*x*x;
    float t = tanh_fast(0.7978845608028654f * fmaf(0.044715f, x3, x));
    return 0.5f * x * (1.f + t);
}

__global__ __launch_bounds__(256, 2) void k_mgemm2(const float* __restrict__ U,
                                                   float* __restrict__ out)
{
    extern __shared__ char smem[];
    uint32_t sb = smem_u32(smem);
    int tid = threadIdx.x, wid = tid >> 5, lane = tid & 31;
    int bn = blockIdx.x * BN, bm = blockIdx.y * BM;
    int m_base = (wid & 1) * 64, n_base = (wid >> 1) * 32;

    float acc[4][4][4];
#pragma unroll
    for (int i = 0; i < 4; i++)
#pragma unroll
        for (int j = 0; j < 4; j++)
#pragma unroll
            for (int q = 0; q < 4; q++) acc[i][j][q] = 0.f;

    gemm_mainloop(sb, tid, lane, m_base, n_base, bm, bn, g_X, g_C, KC, KC/BKT, acc);

    int r0 = lane >> 2, c0 = (lane & 3) * 2;
#pragma unroll
    for (int mi = 0; mi < 4; mi++) {
        int mg = bm + m_base + mi*16 + r0;
#pragma unroll
        for (int ni = 0; ni < 4; ni++) {
            int cg = bn + n_base + ni*8 + c0;
            {
                size_t o = (size_t)mg*HDIM + cg;
                float2 uv = *(const float2*)&U[o];
                float2 r;
                r.x = uv.x + gelu_tanh(acc[mi][ni][0]);
                r.y = uv.y + gelu_tanh(acc[mi][ni][1]);
                *(float2*)&out[o] = r;
            }
            {
                size_t o = (size_t)(mg+8)*HDIM + cg;
                float2 uv = *(const float2*)&U[o];
                float2 r;
                r.x = uv.x + gelu_tanh(acc[mi][ni][2]);
                r.y = uv.y + gelu_tanh(acc[mi][ni][3]);
                *(float2*)&out[o] = r;
            }
        }
    }
}

// ---------------- launch -----------------------------------------------------
extern "C" void kernel_launch(void* const* d_in, const int* in_sizes, int n_in,
                              void* d_out, int out_size)
{
    const float* u    = (const float*)d_in[0];
    const float* llr  = (const float*)d_in[1];
    const float* lim  = (const float*)d_in[2];
    const float* Btr  = (const float*)d_in[3];
    const float* Bti  = (const float*)d_in[4];
    const float* Ctr  = (const float*)d_in[5];
    const float* Cti  = (const float*)d_in[6];
    const float* ld   = (const float*)d_in[7];
    const float* gmma = (const float*)d_in[8];
    const float* beta = (const float*)d_in[9];
    float* out = (float*)d_out;

    cudaFuncSetAttribute(k_mgemm1, cudaFuncAttributeMaxDynamicSharedMemorySize, SMEM_BYTES);
    cudaFuncSetAttribute(k_mgemm2, cudaFuncAttributeMaxDynamicSharedMemorySize, SMEM_BYTES);

    k_params<<<1, 256>>>(llr, lim, ld);
    k_fill<<<KC*HDIM/256, 256>>>(Btr, Bti, Ctr, Cti);
    k_ln<<<MTOT/8, 256>>>(u, gmma, beta);

    k_mgemm1<<<dim3(KC/BN, MTOT/BM), 256, SMEM_BYTES>>>();

    k_scan_ends<<<dim3(NCHUNK/2, BATCH), 256>>>();
    k_scan_chain<<<BATCH, 256>>>();
    k_scan_write<<<dim3(NCHUNK/2, BATCH), 256>>>();

    k_mgemm2<<<dim3(HDIM/BN, MTOT/BM), 256, SMEM_BYTES>>>(u, out);
}